// round 14
// baseline (speedup 1.0000x reference)
#include <cuda_runtime.h>
#include <cuda_fp16.h>
#include <mma.h>
#include <cstdint>
#include <string.h>

using namespace nvcuda;

#define Bn 8
#define Sn 2048
#define Cn 128
#define Hn 4
#define Dn 32
#define HD (Hn*Dn)
#define NSPLIT 4
#define KEYS_PER_SPLIT (Sn/NSPLIT)

// -------------------- scratch ------------------------------------------------
__device__ float g_mu[Bn];
__device__ float g_rstd[Bn];
__device__ float g_part[Bn*8*2];
__device__ __half g_qh[Bn*Hn*Sn*Dn];   // [B,H,S,D], pre-scaled by D^-0.5*log2(e)
__device__ __half g_kh[Bn*Hn*Sn*Dn];
__device__ __half g_vh[Bn*Hn*Sn*Dn];
__device__ float g_po[NSPLIT*Bn*Hn*Sn*Dn];  // partial O (unnormalized, f32)
__device__ float g_pl[NSPLIT*Bn*Hn*Sn];     // partial rowsum
__device__ __half g_oh[Bn*Sn*HD];      // [B,S,H*D] half

// -------------------- kernel 1a: GroupNorm partial sums ----------------------
__global__ __launch_bounds__(256) void gn_part_kernel(const float* __restrict__ x) {
    const int sl = blockIdx.x;
    const int b  = blockIdx.y;
    const int n4 = Sn * Cn / 4;
    const int per = n4 / 8;
    const float4* xb = (const float4*)(x + (size_t)b * Sn * Cn) + sl * per;
    float s = 0.f;
    float ss = 0.f;
    for (int i = threadIdx.x; i < per; i += 256) {
        float4 v = xb[i];
        s  += v.x + v.y + v.z + v.w;
        ss += v.x*v.x + v.y*v.y + v.z*v.z + v.w*v.w;
    }
    __shared__ float sh[256];
    __shared__ float sh2[256];
    sh[threadIdx.x] = s;
    sh2[threadIdx.x] = ss;
    __syncthreads();
    for (int st = 128; st > 0; st >>= 1) {
        if (threadIdx.x < st) {
            sh[threadIdx.x]  += sh[threadIdx.x + st];
            sh2[threadIdx.x] += sh2[threadIdx.x + st];
        }
        __syncthreads();
    }
    if (threadIdx.x == 0) {
        g_part[(b*8 + sl)*2 + 0] = sh[0];
        g_part[(b*8 + sl)*2 + 1] = sh2[0];
    }
}

// -------------------- kernel 1b: GroupNorm finalize --------------------------
__global__ void gn_fin_kernel() {
    int b = threadIdx.x;
    if (b < Bn) {
        float s = 0.f;
        float ss = 0.f;
        for (int i = 0; i < 8; i++) {
            s  += g_part[(b*8 + i)*2 + 0];
            ss += g_part[(b*8 + i)*2 + 1];
        }
        const float inv_n = 1.0f / (float)(Sn * Cn);
        float mu  = s * inv_n;
        float var = ss * inv_n - mu * mu;
        g_mu[b]   = mu;
        g_rstd[b] = rsqrtf(var + 1e-5f);
    }
}

// -------------------- kernel 2: norm + QKV GEMM (half wmma) ------------------
__global__ __launch_bounds__(256) void qkv_wmma_kernel(
    const float* __restrict__ x, const float* __restrict__ gamma,
    const float* __restrict__ beta, const float* __restrict__ w)
{
    __shared__ __half As[128*72];
    __shared__ __half Bs[128*72];
    __shared__ float Scr[8*256];

    const int m0 = blockIdx.x * 128;
    const int part = blockIdx.y;
    const int n0 = part * 128;
    const int b  = m0 >> 11;
    const float mu = g_mu[b];
    const float rstd = g_rstd[b];
    const int t = threadIdx.x;
    const int wid = t >> 5;
    const int lane = t & 31;
    const int wm = wid >> 1;
    const int wn = wid & 1;

    wmma::fragment<wmma::accumulator, 16, 16, 16, float> acc[2][4];
    #pragma unroll
    for (int i = 0; i < 2; i++) {
        #pragma unroll
        for (int j = 0; j < 4; j++) {
            wmma::fill_fragment(acc[i][j], 0.f);
        }
    }

    for (int kc = 0; kc < Cn; kc += 64) {
        __syncthreads();
        #pragma unroll
        for (int it = 0; it < 8; it++) {
            int idx = it * 256 + t;
            int r = idx >> 4;
            int c4 = idx & 15;
            float4 xv = *(const float4*)(x + (size_t)(m0 + r) * Cn + kc + c4 * 4);
            float4 gv = *(const float4*)(gamma + kc + c4 * 4);
            float4 bv = *(const float4*)(beta  + kc + c4 * 4);
            __half* ap = As + r*72 + c4*4;
            ap[0] = __float2half((xv.x - mu) * rstd * gv.x + bv.x);
            ap[1] = __float2half((xv.y - mu) * rstd * gv.y + bv.y);
            ap[2] = __float2half((xv.z - mu) * rstd * gv.z + bv.z);
            ap[3] = __float2half((xv.w - mu) * rstd * gv.w + bv.w);
            float4 wv = *(const float4*)(w + (size_t)(n0 + r) * Cn + kc + c4 * 4);
            __half* bp = Bs + r*72 + c4*4;
            bp[0] = __float2half(wv.x);
            bp[1] = __float2half(wv.y);
            bp[2] = __float2half(wv.z);
            bp[3] = __float2half(wv.w);
        }
        __syncthreads();
        #pragma unroll
        for (int ks = 0; ks < 4; ks++) {
            wmma::fragment<wmma::matrix_a, 16, 16, 16, __half, wmma::row_major> af[2];
            #pragma unroll
            for (int i = 0; i < 2; i++) {
                wmma::load_matrix_sync(af[i], As + (wm*32 + i*16)*72 + ks*16, 72);
            }
            #pragma unroll
            for (int j = 0; j < 4; j++) {
                wmma::fragment<wmma::matrix_b, 16, 16, 16, __half, wmma::col_major> bf;
                wmma::load_matrix_sync(bf, Bs + (wn*64 + j*16)*72 + ks*16, 72);
                wmma::mma_sync(acc[0][j], af[0], bf, acc[0][j]);
                wmma::mma_sync(acc[1][j], af[1], bf, acc[1][j]);
            }
        }
    }

    const float qscale = 0.17677669529663689f * 1.4426950408889634f;
    const float scale = (part == 0) ? qscale : 1.0f;
    __half* dstbase = (part == 0) ? g_qh : ((part == 1) ? g_kh : g_vh);
    float* scr = Scr + wid * 256;
    const int r = lane & 15;
    const int ch = lane >> 4;
    #pragma unroll
    for (int i = 0; i < 2; i++) {
        #pragma unroll
        for (int j = 0; j < 4; j++) {
            wmma::store_matrix_sync(scr, acc[i][j], 16, wmma::mem_row_major);
            __syncwarp();
            int m = m0 + wm*32 + i*16 + r;
            int s = m & (Sn - 1);
            int nb = wn*64 + j*16 + ch*8;
            int h = nb >> 5;
            int d = nb & 31;
            __half tmp[8];
            #pragma unroll
            for (int cc = 0; cc < 8; cc++) {
                tmp[cc] = __float2half(scr[r*16 + ch*8 + cc] * scale);
            }
            __half* dst = dstbase + (((size_t)(b*Hn + h)) * Sn + s) * Dn + d;
            *(uint4*)dst = *(uint4*)tmp;
            __syncwarp();
        }
    }
}

// -------------------- kernel 3: flash attention (split-K x4) -----------------
// grid (S/128, H, B*4), block 128 = 4 warps, 32 q-rows per warp
__global__ __launch_bounds__(128) void attn_wmma_kernel() {
    __shared__ __half SB[2*64*40];          // Ks + Vs (pitch 40); Q staged here first
    __shared__ __half Ones[16*24];          // 16x16 block, col 0 = 1.0 (pitch 24)
    __shared__ __half Pb[4*2*16*72];        // per-warp 2 P tiles / epilogue scratch

    const int qt = blockIdx.x;
    const int h  = blockIdx.y;
    const int bz = blockIdx.z;
    const int b  = bz >> 2;
    const int split = bz & 3;
    const int bh = b * Hn + h;
    const size_t base = (size_t)bh * Sn * Dn;
    const int t = threadIdx.x;
    const int wid = t >> 5;
    const int lane = t & 31;

    __half* Ks = SB;
    __half* Vs = SB + 64*40;
    __half* Pw = Pb + wid * 2 * 16 * 72;

    // stage Q (128 x 32 half) over Ks|Vs, pitch 40; init Ones block
    {
        const uint4* qsrc = (const uint4*)(g_qh + base + (size_t)qt * 128 * Dn);
        #pragma unroll
        for (int it = 0; it < 4; it++) {
            int idx = it * 128 + t;
            int r = idx >> 2;
            int c = idx & 3;
            *(uint4*)&SB[r*40 + c*8] = qsrc[idx];
        }
        if (t < 48) {
            int r = t / 3;
            int c8 = t - r * 3;
            __half z[8];
            #pragma unroll
            for (int j = 0; j < 8; j++) {
                z[j] = __float2half(0.f);
            }
            if (c8 == 0) {
                z[0] = __float2half(1.f);
            }
            *(uint4*)&Ones[r*24 + c8*8] = *(uint4*)z;
        }
    }
    __syncthreads();

    wmma::fragment<wmma::matrix_a, 16, 16, 16, __half, wmma::row_major> qfrag[2][2];
    #pragma unroll
    for (int qg = 0; qg < 2; qg++) {
        #pragma unroll
        for (int kc = 0; kc < 2; kc++) {
            wmma::load_matrix_sync(qfrag[qg][kc], SB + (wid*32 + qg*16)*40 + kc*16, 40);
        }
    }
    wmma::fragment<wmma::matrix_b, 16, 16, 16, __half, wmma::row_major> onesfrag;
    wmma::load_matrix_sync(onesfrag, Ones, 24);
    __syncthreads();

    // persistent accumulators
    wmma::fragment<wmma::accumulator, 16, 16, 16, float> oacc[2][2];
    wmma::fragment<wmma::accumulator, 16, 16, 16, float> racc[2];
    #pragma unroll
    for (int qg = 0; qg < 2; qg++) {
        wmma::fill_fragment(oacc[qg][0], 0.f);
        wmma::fill_fragment(oacc[qg][1], 0.f);
        wmma::fill_fragment(racc[qg], 0.f);
    }

    const uint4* ksrc = (const uint4*)(g_kh + base + (size_t)split * KEYS_PER_SPLIT * Dn);
    const uint4* vsrc = (const uint4*)(g_vh + base + (size_t)split * KEYS_PER_SPLIT * Dn);
    const int c_s = t & 3;
    uint4 kreg[2];
    uint4 vreg[2];
    #pragma unroll
    for (int it = 0; it < 2; it++) {
        kreg[it] = ksrc[it*128 + t];
        vreg[it] = vsrc[it*128 + t];
    }

    const int NT = KEYS_PER_SPLIT / 64;   // 8
    for (int kb = 0; kb < NT; kb++) {
        __syncthreads();
        #pragma unroll
        for (int it = 0; it < 2; it++) {
            int r = (it * 128 + t) >> 2;
            *(uint4*)&Ks[r*40 + c_s*8] = kreg[it];
            *(uint4*)&Vs[r*40 + c_s*8] = vreg[it];
        }
        __syncthreads();
        if (kb + 1 < NT) {
            #pragma unroll
            for (int it = 0; it < 2; it++) {
                kreg[it] = ksrc[(kb+1)*256 + it*128 + t];
                vreg[it] = vsrc[(kb+1)*256 + it*128 + t];
            }
        }

        // S = Q K^T for both q-groups (kfrag loaded once per nt, used twice)
        #pragma unroll
        for (int nt = 0; nt < 4; nt++) {
            wmma::fragment<wmma::matrix_b, 16, 16, 16, __half, wmma::col_major> kf0;
            wmma::fragment<wmma::matrix_b, 16, 16, 16, __half, wmma::col_major> kf1;
            wmma::load_matrix_sync(kf0, Ks + (nt*16)*40, 40);
            wmma::load_matrix_sync(kf1, Ks + (nt*16)*40 + 16, 40);
            #pragma unroll
            for (int qg = 0; qg < 2; qg++) {
                wmma::fragment<wmma::accumulator, 16, 16, 16, __half> cacc;
                wmma::fill_fragment(cacc, __float2half(0.f));
                wmma::mma_sync(cacc, qfrag[qg][0], kf0, cacc);
                wmma::mma_sync(cacc, qfrag[qg][1], kf1, cacc);
                #pragma unroll
                for (int i = 0; i < cacc.num_elements / 2; i++) {
                    __half2 hv = __halves2half2(cacc.x[2*i], cacc.x[2*i+1]);
                    hv = h2exp2(hv);
                    cacc.x[2*i]   = __low2half(hv);
                    cacc.x[2*i+1] = __high2half(hv);
                }
                wmma::store_matrix_sync(Pw + qg*(16*72) + nt*16, cacc, 72, wmma::mem_row_major);
            }
        }
        __syncwarp();

        // O += P V ; rowsum += P ones
        #pragma unroll
        for (int kc = 0; kc < 4; kc++) {
            wmma::fragment<wmma::matrix_a, 16, 16, 16, __half, wmma::row_major> pf0;
            wmma::fragment<wmma::matrix_a, 16, 16, 16, __half, wmma::row_major> pf1;
            wmma::load_matrix_sync(pf0, Pw + kc*16, 72);
            wmma::load_matrix_sync(pf1, Pw + 16*72 + kc*16, 72);
            wmma::fragment<wmma::matrix_b, 16, 16, 16, __half, wmma::row_major> vfrag;
            wmma::load_matrix_sync(vfrag, Vs + (kc*16)*40, 40);
            wmma::mma_sync(oacc[0][0], pf0, vfrag, oacc[0][0]);
            wmma::mma_sync(oacc[1][0], pf1, vfrag, oacc[1][0]);
            wmma::load_matrix_sync(vfrag, Vs + (kc*16)*40 + 16, 40);
            wmma::mma_sync(oacc[0][1], pf0, vfrag, oacc[0][1]);
            wmma::mma_sync(oacc[1][1], pf1, vfrag, oacc[1][1]);
            wmma::mma_sync(racc[0], pf0, onesfrag, racc[0]);
            wmma::mma_sync(racc[1], pf1, onesfrag, racc[1]);
        }
        __syncwarp();
    }

    // epilogue: write f32 partial O directly from fragments, rowsum via smem
    float* pobase = g_po + ((size_t)split * (Bn*Hn) + bh) * Sn * Dn;
    float* plbase = g_pl + ((size_t)split * (Bn*Hn) + bh) * Sn;
    float* scr = (float*)Pw;
    #pragma unroll
    for (int qg = 0; qg < 2; qg++) {
        int qrow0 = qt*128 + wid*32 + qg*16;
        wmma::store_matrix_sync(pobase + (size_t)qrow0 * Dn,      oacc[qg][0], Dn, wmma::mem_row_major);
        wmma::store_matrix_sync(pobase + (size_t)qrow0 * Dn + 16, oacc[qg][1], Dn, wmma::mem_row_major);
        wmma::store_matrix_sync(scr, racc[qg], 16, wmma::mem_row_major);
        __syncwarp();
        if (lane < 16) {
            plbase[qrow0 + lane] = scr[lane*16];
        }
        __syncwarp();
    }
}

// -------------------- kernel 3b: split-K combine (4 partials) ----------------
// grid 1024, block 256; each thread handles 8 d-values
__global__ __launch_bounds__(256) void attn_combine_kernel() {
    int idx = blockIdx.x * 256 + threadIdx.x;     // 0 .. 262143
    int d8 = idx & 3;
    int s  = (idx >> 2) & (Sn - 1);
    int hh = (idx >> 13) & (Hn - 1);
    int b  = idx >> 15;
    int bh = b * Hn + hh;

    const size_t stride_o = (size_t)(Bn*Hn) * Sn * Dn;
    const size_t stride_l = (size_t)(Bn*Hn) * Sn;
    size_t pobase = ((size_t)bh * Sn + s) * Dn + d8 * 8;
    size_t plbase = (size_t)bh * Sn + s;

    float acc[8];
    #pragma unroll
    for (int j = 0; j < 8; j++) {
        acc[j] = 0.f;
    }
    float l = 0.f;
    #pragma unroll
    for (int sp = 0; sp < NSPLIT; sp++) {
        const float4* p = (const float4*)(g_po + sp * stride_o + pobase);
        float4 a0 = p[0];
        float4 a1 = p[1];
        acc[0] += a0.x;
        acc[1] += a0.y;
        acc[2] += a0.z;
        acc[3] += a0.w;
        acc[4] += a1.x;
        acc[5] += a1.y;
        acc[6] += a1.z;
        acc[7] += a1.w;
        l += g_pl[sp * stride_l + plbase];
    }
    float il = 1.0f / l;
    __half tmp[8];
    #pragma unroll
    for (int j = 0; j < 8; j++) {
        tmp[j] = __float2half(acc[j] * il);
    }
    __half* dst = g_oh + ((size_t)b * Sn + s) * HD + hh * Dn + d8 * 8;
    *(uint4*)dst = *(uint4*)tmp;
}

// -------------------- kernel 4: out projection (half wmma) + residual --------
__global__ __launch_bounds__(256) void out_wmma_kernel(
    const float* __restrict__ x, const float* __restrict__ w,
    const float* __restrict__ bias, float* __restrict__ out)
{
    __shared__ __half As[128*72];
    __shared__ __half Bs[128*72];
    __shared__ float Scr[8*256];

    const int m0 = blockIdx.x * 128;
    const int t = threadIdx.x;
    const int wid = t >> 5;
    const int lane = t & 31;
    const int wm = wid >> 1;
    const int wn = wid & 1;

    wmma::fragment<wmma::accumulator, 16, 16, 16, float> acc[2][4];
    #pragma unroll
    for (int i = 0; i < 2; i++) {
        #pragma unroll
        for (int j = 0; j < 4; j++) {
            wmma::fill_fragment(acc[i][j], 0.f);
        }
    }

    for (int kc = 0; kc < HD; kc += 64) {
        __syncthreads();
        #pragma unroll
        for (int it = 0; it < 4; it++) {
            int idx = it * 256 + t;
            int r = idx >> 3;
            int c8 = idx & 7;
            *(uint4*)&As[r*72 + c8*8] =
                *(const uint4*)(g_oh + (size_t)(m0 + r) * HD + kc + c8*8);
        }
        #pragma unroll
        for (int it = 0; it < 8; it++) {
            int idx = it * 256 + t;
            int r = idx >> 4;
            int c4 = idx & 15;
            float4 wv = *(const float4*)(w + (size_t)r * HD + kc + c4 * 4);
            __half* bp = Bs + r*72 + c4*4;
            bp[0] = __float2half(wv.x);
            bp[1] = __float2half(wv.y);
            bp[2] = __float2half(wv.z);
            bp[3] = __float2half(wv.w);
        }
        __syncthreads();
        #pragma unroll
        for (int ks = 0; ks < 4; ks++) {
            wmma::fragment<wmma::matrix_a, 16, 16, 16, __half, wmma::row_major> af[2];
            #pragma unroll
            for (int i = 0; i < 2; i++) {
                wmma::load_matrix_sync(af[i], As + (wm*32 + i*16)*72 + ks*16, 72);
            }
            #pragma unroll
            for (int j = 0; j < 4; j++) {
                wmma::fragment<wmma::matrix_b, 16, 16, 16, __half, wmma::col_major> bf;
                wmma::load_matrix_sync(bf, Bs + (wn*64 + j*16)*72 + ks*16, 72);
                wmma::mma_sync(acc[0][j], af[0], bf, acc[0][j]);
                wmma::mma_sync(acc[1][j], af[1], bf, acc[1][j]);
            }
        }
    }

    float* scr = Scr + wid * 256;
    const int r = lane & 15;
    const int ch = lane >> 4;
    #pragma unroll
    for (int i = 0; i < 2; i++) {
        #pragma unroll
        for (int j = 0; j < 4; j++) {
            wmma::store_matrix_sync(scr, acc[i][j], 16, wmma::mem_row_major);
            __syncwarp();
            int m = m0 + wm*32 + i*16 + r;
            int nb = wn*64 + j*16 + ch*8;
            float4 x0 = *(const float4*)(x + (size_t)m * Cn + nb);
            float4 x1 = *(const float4*)(x + (size_t)m * Cn + nb + 4);
            float4 b0 = *(const float4*)(bias + nb);
            float4 b1 = *(const float4*)(bias + nb + 4);
            float4 o0;
            float4 o1;
            o0.x = scr[r*16 + ch*8 + 0] + b0.x + x0.x;
            o0.y = scr[r*16 + ch*8 + 1] + b0.y + x0.y;
            o0.z = scr[r*16 + ch*8 + 2] + b0.z + x0.z;
            o0.w = scr[r*16 + ch*8 + 3] + b0.w + x0.w;
            o1.x = scr[r*16 + ch*8 + 4] + b1.x + x1.x;
            o1.y = scr[r*16 + ch*8 + 5] + b1.y + x1.y;
            o1.z = scr[r*16 + ch*8 + 6] + b1.z + x1.z;
            o1.w = scr[r*16 + ch*8 + 7] + b1.w + x1.w;
            *(float4*)(out + (size_t)m * Cn + nb) = o0;
            *(float4*)(out + (size_t)m * Cn + nb + 4) = o1;
            __syncwarp();
        }
    }
}

// -------------------- launch -------------------------------------------------
extern "C" void kernel_launch(void* const* d_in, const int* in_sizes, int n_in,
                              void* d_out, int out_size) {
    const float* x     = (const float*)d_in[0];
    const float* gamma = (const float*)d_in[1];
    const float* beta  = (const float*)d_in[2];
    const float* w_qkv = (const float*)d_in[3];
    const float* w_out = (const float*)d_in[4];
    const float* b_out = (const float*)d_in[5];
    float* out = (float*)d_out;

    gn_part_kernel<<<dim3(8, Bn), 256>>>(x);
    gn_fin_kernel<<<1, 32>>>();
    qkv_wmma_kernel<<<dim3(128, 3), 256>>>(x, gamma, beta, w_qkv);
    attn_wmma_kernel<<<dim3(Sn / 128, Hn, Bn * NSPLIT), 128>>>();
    attn_combine_kernel<<<1024, 256>>>();
    out_wmma_kernel<<<128, 256>>>(x, w_out, b_out, out);
}

// round 15
// speedup vs baseline: 1.0272x; 1.0272x over previous
#include <cuda_runtime.h>
#include <cuda_fp16.h>
#include <mma.h>
#include <cstdint>
#include <string.h>

using namespace nvcuda;

#define Bn 8
#define Sn 2048
#define Cn 128
#define Hn 4
#define Dn 32
#define HD (Hn*Dn)
#define NSPLIT 2
#define KEYS_PER_SPLIT (Sn/NSPLIT)

// -------------------- scratch ------------------------------------------------
__device__ float g_mu[Bn];
__device__ float g_rstd[Bn];
__device__ float g_part[Bn*8*2];
__device__ __half g_qh[Bn*Hn*Sn*Dn];   // [B,H,S,D], pre-scaled by D^-0.5*log2(e)
__device__ __half g_kh[Bn*Hn*Sn*Dn];
__device__ __half g_vh[Bn*Hn*Sn*Dn];
__device__ float g_po[NSPLIT*Bn*Hn*Sn*Dn];  // partial O (unnormalized, f32)
__device__ float g_pl[NSPLIT*Bn*Hn*Sn];     // partial rowsum

// -------------------- kernel 1a: GroupNorm partial sums ----------------------
__global__ __launch_bounds__(256) void gn_part_kernel(const float* __restrict__ x) {
    const int sl = blockIdx.x;
    const int b  = blockIdx.y;
    const int n4 = Sn * Cn / 4;
    const int per = n4 / 8;
    const float4* xb = (const float4*)(x + (size_t)b * Sn * Cn) + sl * per;
    float s = 0.f;
    float ss = 0.f;
    for (int i = threadIdx.x; i < per; i += 256) {
        float4 v = xb[i];
        s  += v.x + v.y + v.z + v.w;
        ss += v.x*v.x + v.y*v.y + v.z*v.z + v.w*v.w;
    }
    __shared__ float sh[256];
    __shared__ float sh2[256];
    sh[threadIdx.x] = s;
    sh2[threadIdx.x] = ss;
    __syncthreads();
    for (int st = 128; st > 0; st >>= 1) {
        if (threadIdx.x < st) {
            sh[threadIdx.x]  += sh[threadIdx.x + st];
            sh2[threadIdx.x] += sh2[threadIdx.x + st];
        }
        __syncthreads();
    }
    if (threadIdx.x == 0) {
        g_part[(b*8 + sl)*2 + 0] = sh[0];
        g_part[(b*8 + sl)*2 + 1] = sh2[0];
    }
}

// -------------------- kernel 1b: GroupNorm finalize --------------------------
__global__ void gn_fin_kernel() {
    int b = threadIdx.x;
    if (b < Bn) {
        float s = 0.f;
        float ss = 0.f;
        for (int i = 0; i < 8; i++) {
            s  += g_part[(b*8 + i)*2 + 0];
            ss += g_part[(b*8 + i)*2 + 1];
        }
        const float inv_n = 1.0f / (float)(Sn * Cn);
        float mu  = s * inv_n;
        float var = ss * inv_n - mu * mu;
        g_mu[b]   = mu;
        g_rstd[b] = rsqrtf(var + 1e-5f);
    }
}

// -------------------- kernel 2: norm + QKV GEMM (half wmma) ------------------
__global__ __launch_bounds__(256) void qkv_wmma_kernel(
    const float* __restrict__ x, const float* __restrict__ gamma,
    const float* __restrict__ beta, const float* __restrict__ w)
{
    __shared__ __half As[128*72];
    __shared__ __half Bs[128*72];
    __shared__ float Scr[8*256];

    const int m0 = blockIdx.x * 128;
    const int part = blockIdx.y;
    const int n0 = part * 128;
    const int b  = m0 >> 11;
    const float mu = g_mu[b];
    const float rstd = g_rstd[b];
    const int t = threadIdx.x;
    const int wid = t >> 5;
    const int lane = t & 31;
    const int wm = wid >> 1;
    const int wn = wid & 1;

    wmma::fragment<wmma::accumulator, 16, 16, 16, float> acc[2][4];
    #pragma unroll
    for (int i = 0; i < 2; i++) {
        #pragma unroll
        for (int j = 0; j < 4; j++) {
            wmma::fill_fragment(acc[i][j], 0.f);
        }
    }

    for (int kc = 0; kc < Cn; kc += 64) {
        __syncthreads();
        #pragma unroll
        for (int it = 0; it < 8; it++) {
            int idx = it * 256 + t;
            int r = idx >> 4;
            int c4 = idx & 15;
            float4 xv = *(const float4*)(x + (size_t)(m0 + r) * Cn + kc + c4 * 4);
            float4 gv = *(const float4*)(gamma + kc + c4 * 4);
            float4 bv = *(const float4*)(beta  + kc + c4 * 4);
            __half* ap = As + r*72 + c4*4;
            ap[0] = __float2half((xv.x - mu) * rstd * gv.x + bv.x);
            ap[1] = __float2half((xv.y - mu) * rstd * gv.y + bv.y);
            ap[2] = __float2half((xv.z - mu) * rstd * gv.z + bv.z);
            ap[3] = __float2half((xv.w - mu) * rstd * gv.w + bv.w);
            float4 wv = *(const float4*)(w + (size_t)(n0 + r) * Cn + kc + c4 * 4);
            __half* bp = Bs + r*72 + c4*4;
            bp[0] = __float2half(wv.x);
            bp[1] = __float2half(wv.y);
            bp[2] = __float2half(wv.z);
            bp[3] = __float2half(wv.w);
        }
        __syncthreads();
        #pragma unroll
        for (int ks = 0; ks < 4; ks++) {
            wmma::fragment<wmma::matrix_a, 16, 16, 16, __half, wmma::row_major> af[2];
            #pragma unroll
            for (int i = 0; i < 2; i++) {
                wmma::load_matrix_sync(af[i], As + (wm*32 + i*16)*72 + ks*16, 72);
            }
            #pragma unroll
            for (int j = 0; j < 4; j++) {
                wmma::fragment<wmma::matrix_b, 16, 16, 16, __half, wmma::col_major> bf;
                wmma::load_matrix_sync(bf, Bs + (wn*64 + j*16)*72 + ks*16, 72);
                wmma::mma_sync(acc[0][j], af[0], bf, acc[0][j]);
                wmma::mma_sync(acc[1][j], af[1], bf, acc[1][j]);
            }
        }
    }

    const float qscale = 0.17677669529663689f * 1.4426950408889634f;
    const float scale = (part == 0) ? qscale : 1.0f;
    __half* dstbase = (part == 0) ? g_qh : ((part == 1) ? g_kh : g_vh);
    float* scr = Scr + wid * 256;
    const int r = lane & 15;
    const int ch = lane >> 4;
    #pragma unroll
    for (int i = 0; i < 2; i++) {
        #pragma unroll
        for (int j = 0; j < 4; j++) {
            wmma::store_matrix_sync(scr, acc[i][j], 16, wmma::mem_row_major);
            __syncwarp();
            int m = m0 + wm*32 + i*16 + r;
            int s = m & (Sn - 1);
            int nb = wn*64 + j*16 + ch*8;
            int h = nb >> 5;
            int d = nb & 31;
            __half tmp[8];
            #pragma unroll
            for (int cc = 0; cc < 8; cc++) {
                tmp[cc] = __float2half(scr[r*16 + ch*8 + cc] * scale);
            }
            __half* dst = dstbase + (((size_t)(b*Hn + h)) * Sn + s) * Dn + d;
            *(uint4*)dst = *(uint4*)tmp;
            __syncwarp();
        }
    }
}

// -------------------- kernel 3: flash attention (split-K x2, no rowsum MMA) --
// grid (S/128, H, B*2), block 128 = 4 warps, 32 q-rows per warp
__global__ __launch_bounds__(128) void attn_wmma_kernel() {
    __shared__ __half SB[2*64*40];          // Ks + Vs (pitch 40); Q staged here first
    __shared__ __half Pb[4*2*16*72];        // per-warp 2 P tiles / epilogue scratch

    const int qt = blockIdx.x;
    const int h  = blockIdx.y;
    const int bz = blockIdx.z;
    const int b  = bz >> 1;
    const int split = bz & 1;
    const int bh = b * Hn + h;
    const size_t base = (size_t)bh * Sn * Dn;
    const int t = threadIdx.x;
    const int wid = t >> 5;
    const int lane = t & 31;

    __half* Ks = SB;
    __half* Vs = SB + 64*40;
    __half* Pw = Pb + wid * 2 * 16 * 72;

    // stage Q (128 x 32 half) over Ks|Vs, pitch 40
    {
        const uint4* qsrc = (const uint4*)(g_qh + base + (size_t)qt * 128 * Dn);
        #pragma unroll
        for (int it = 0; it < 4; it++) {
            int idx = it * 128 + t;
            int r = idx >> 2;
            int c = idx & 3;
            *(uint4*)&SB[r*40 + c*8] = qsrc[idx];
        }
    }
    __syncthreads();

    wmma::fragment<wmma::matrix_a, 16, 16, 16, __half, wmma::row_major> qfrag[2][2];
    #pragma unroll
    for (int qg = 0; qg < 2; qg++) {
        #pragma unroll
        for (int kc = 0; kc < 2; kc++) {
            wmma::load_matrix_sync(qfrag[qg][kc], SB + (wid*32 + qg*16)*40 + kc*16, 40);
        }
    }
    __syncthreads();

    // persistent accumulators: O fragments + elementwise float rowsums
    wmma::fragment<wmma::accumulator, 16, 16, 16, float> oacc[2][2];
    #pragma unroll
    for (int qg = 0; qg < 2; qg++) {
        wmma::fill_fragment(oacc[qg][0], 0.f);
        wmma::fill_fragment(oacc[qg][1], 0.f);
    }
    float rsumf[2][8];
    #pragma unroll
    for (int qg = 0; qg < 2; qg++) {
        #pragma unroll
        for (int i = 0; i < 8; i++) {
            rsumf[qg][i] = 0.f;
        }
    }

    const uint4* ksrc = (const uint4*)(g_kh + base + (size_t)split * KEYS_PER_SPLIT * Dn);
    const uint4* vsrc = (const uint4*)(g_vh + base + (size_t)split * KEYS_PER_SPLIT * Dn);
    const int c_s = t & 3;
    uint4 kreg[2];
    uint4 vreg[2];
    #pragma unroll
    for (int it = 0; it < 2; it++) {
        kreg[it] = ksrc[it*128 + t];
        vreg[it] = vsrc[it*128 + t];
    }

    const int NT = KEYS_PER_SPLIT / 64;   // 16
    for (int kb = 0; kb < NT; kb++) {
        __syncthreads();
        #pragma unroll
        for (int it = 0; it < 2; it++) {
            int r = (it * 128 + t) >> 2;
            *(uint4*)&Ks[r*40 + c_s*8] = kreg[it];
            *(uint4*)&Vs[r*40 + c_s*8] = vreg[it];
        }
        __syncthreads();
        if (kb + 1 < NT) {
            #pragma unroll
            for (int it = 0; it < 2; it++) {
                kreg[it] = ksrc[(kb+1)*256 + it*128 + t];
                vreg[it] = vsrc[(kb+1)*256 + it*128 + t];
            }
        }

        // S = Q K^T; exp in-fragment; rowsum accumulated elementwise in f32
        #pragma unroll
        for (int nt = 0; nt < 4; nt++) {
            wmma::fragment<wmma::matrix_b, 16, 16, 16, __half, wmma::col_major> kf0;
            wmma::fragment<wmma::matrix_b, 16, 16, 16, __half, wmma::col_major> kf1;
            wmma::load_matrix_sync(kf0, Ks + (nt*16)*40, 40);
            wmma::load_matrix_sync(kf1, Ks + (nt*16)*40 + 16, 40);
            #pragma unroll
            for (int qg = 0; qg < 2; qg++) {
                wmma::fragment<wmma::accumulator, 16, 16, 16, __half> cacc;
                wmma::fill_fragment(cacc, __float2half(0.f));
                wmma::mma_sync(cacc, qfrag[qg][0], kf0, cacc);
                wmma::mma_sync(cacc, qfrag[qg][1], kf1, cacc);
                #pragma unroll
                for (int i = 0; i < cacc.num_elements / 2; i++) {
                    __half2 hv = __halves2half2(cacc.x[2*i], cacc.x[2*i+1]);
                    hv = h2exp2(hv);
                    cacc.x[2*i]   = __low2half(hv);
                    cacc.x[2*i+1] = __high2half(hv);
                    rsumf[qg][2*i]   += __half2float(cacc.x[2*i]);
                    rsumf[qg][2*i+1] += __half2float(cacc.x[2*i+1]);
                }
                wmma::store_matrix_sync(Pw + qg*(16*72) + nt*16, cacc, 72, wmma::mem_row_major);
            }
        }
        __syncwarp();

        // O += P V
        #pragma unroll
        for (int kc = 0; kc < 4; kc++) {
            wmma::fragment<wmma::matrix_a, 16, 16, 16, __half, wmma::row_major> pf0;
            wmma::fragment<wmma::matrix_a, 16, 16, 16, __half, wmma::row_major> pf1;
            wmma::load_matrix_sync(pf0, Pw + kc*16, 72);
            wmma::load_matrix_sync(pf1, Pw + 16*72 + kc*16, 72);
            wmma::fragment<wmma::matrix_b, 16, 16, 16, __half, wmma::row_major> vfrag;
            wmma::load_matrix_sync(vfrag, Vs + (kc*16)*40, 40);
            wmma::mma_sync(oacc[0][0], pf0, vfrag, oacc[0][0]);
            wmma::mma_sync(oacc[1][0], pf1, vfrag, oacc[1][0]);
            wmma::load_matrix_sync(vfrag, Vs + (kc*16)*40 + 16, 40);
            wmma::mma_sync(oacc[0][1], pf0, vfrag, oacc[0][1]);
            wmma::mma_sync(oacc[1][1], pf1, vfrag, oacc[1][1]);
        }
        __syncwarp();
    }

    // epilogue: O partials direct to gmem; rowsums via half-acc fragment store
    // (same fragment type as cacc -> guaranteed identical element mapping)
    float* pobase = g_po + ((size_t)split * (Bn*Hn) + bh) * Sn * Dn;
    float* plbase = g_pl + ((size_t)split * (Bn*Hn) + bh) * Sn;
    __half* scrh = Pw;
    #pragma unroll
    for (int qg = 0; qg < 2; qg++) {
        int qrow0 = qt*128 + wid*32 + qg*16;
        wmma::store_matrix_sync(pobase + (size_t)qrow0 * Dn,      oacc[qg][0], Dn, wmma::mem_row_major);
        wmma::store_matrix_sync(pobase + (size_t)qrow0 * Dn + 16, oacc[qg][1], Dn, wmma::mem_row_major);

        wmma::fragment<wmma::accumulator, 16, 16, 16, __half> hsum;
        #pragma unroll
        for (int i = 0; i < hsum.num_elements; i++) {
            hsum.x[i] = __float2half(rsumf[qg][i]);
        }
        wmma::store_matrix_sync(scrh, hsum, 16, wmma::mem_row_major);
        __syncwarp();
        if (lane < 16) {
            float l = 0.f;
            #pragma unroll
            for (int c = 0; c < 16; c++) {
                l += __half2float(scrh[lane*16 + c]);
            }
            plbase[qrow0 + lane] = l;
        }
        __syncwarp();
    }
}

// -------------------- kernel 4: combine + out projection + residual ----------
// grid (128), block 256; A tile built from 2 split partials (normalize inline)
__global__ __launch_bounds__(256) void out_wmma_kernel(
    const float* __restrict__ x, const float* __restrict__ w,
    const float* __restrict__ bias, float* __restrict__ out)
{
    __shared__ __half As[128*72];
    __shared__ __half Bs[128*72];
    __shared__ float Scr[8*256];

    const int m0 = blockIdx.x * 128;
    const int t = threadIdx.x;
    const int wid = t >> 5;
    const int lane = t & 31;
    const int wm = wid >> 1;
    const int wn = wid & 1;

    const size_t stride_o = (size_t)(Bn*Hn) * Sn * Dn;
    const size_t stride_l = (size_t)(Bn*Hn) * Sn;

    wmma::fragment<wmma::accumulator, 16, 16, 16, float> acc[2][4];
    #pragma unroll
    for (int i = 0; i < 2; i++) {
        #pragma unroll
        for (int j = 0; j < 4; j++) {
            wmma::fill_fragment(acc[i][j], 0.f);
        }
    }

    for (int kc = 0; kc < HD; kc += 64) {
        __syncthreads();
        // A: combine 2 split partials, normalize, convert to half
        #pragma unroll
        for (int it = 0; it < 4; it++) {
            int idx = it * 256 + t;       // 0..1023, 8 cols each
            int r = idx >> 3;
            int c8 = idx & 7;
            int m = m0 + r;
            int b = m >> 11;
            int s = m & (Sn - 1);
            int col = kc + c8*8;
            int h = col >> 5;
            int d = col & 31;
            size_t po_off = ((size_t)(b*Hn + h) * Sn + s) * Dn + d;
            size_t pl_off = (size_t)(b*Hn + h) * Sn + s;
            const float4* p0 = (const float4*)(g_po + po_off);
            const float4* p1 = (const float4*)(g_po + stride_o + po_off);
            float il = 1.0f / (g_pl[pl_off] + g_pl[stride_l + pl_off]);
            float4 a0 = p0[0];
            float4 a1 = p0[1];
            float4 b0 = p1[0];
            float4 b1 = p1[1];
            __half tmp[8];
            tmp[0] = __float2half((a0.x + b0.x) * il);
            tmp[1] = __float2half((a0.y + b0.y) * il);
            tmp[2] = __float2half((a0.z + b0.z) * il);
            tmp[3] = __float2half((a0.w + b0.w) * il);
            tmp[4] = __float2half((a1.x + b1.x) * il);
            tmp[5] = __float2half((a1.y + b1.y) * il);
            tmp[6] = __float2half((a1.z + b1.z) * il);
            tmp[7] = __float2half((a1.w + b1.w) * il);
            *(uint4*)&As[r*72 + c8*8] = *(uint4*)tmp;
        }
        // B: w f32 -> half
        #pragma unroll
        for (int it = 0; it < 8; it++) {
            int idx = it * 256 + t;
            int r = idx >> 4;
            int c4 = idx & 15;
            float4 wv = *(const float4*)(w + (size_t)r * HD + kc + c4 * 4);
            __half* bp = Bs + r*72 + c4*4;
            bp[0] = __float2half(wv.x);
            bp[1] = __float2half(wv.y);
            bp[2] = __float2half(wv.z);
            bp[3] = __float2half(wv.w);
        }
        __syncthreads();
        #pragma unroll
        for (int ks = 0; ks < 4; ks++) {
            wmma::fragment<wmma::matrix_a, 16, 16, 16, __half, wmma::row_major> af[2];
            #pragma unroll
            for (int i = 0; i < 2; i++) {
                wmma::load_matrix_sync(af[i], As + (wm*32 + i*16)*72 + ks*16, 72);
            }
            #pragma unroll
            for (int j = 0; j < 4; j++) {
                wmma::fragment<wmma::matrix_b, 16, 16, 16, __half, wmma::col_major> bf;
                wmma::load_matrix_sync(bf, Bs + (wn*64 + j*16)*72 + ks*16, 72);
                wmma::mma_sync(acc[0][j], af[0], bf, acc[0][j]);
                wmma::mma_sync(acc[1][j], af[1], bf, acc[1][j]);
            }
        }
    }

    float* scr = Scr + wid * 256;
    const int r = lane & 15;
    const int ch = lane >> 4;
    #pragma unroll
    for (int i = 0; i < 2; i++) {
        #pragma unroll
        for (int j = 0; j < 4; j++) {
            wmma::store_matrix_sync(scr, acc[i][j], 16, wmma::mem_row_major);
            __syncwarp();
            int m = m0 + wm*32 + i*16 + r;
            int nb = wn*64 + j*16 + ch*8;
            float4 x0 = *(const float4*)(x + (size_t)m * Cn + nb);
            float4 x1 = *(const float4*)(x + (size_t)m * Cn + nb + 4);
            float4 b0 = *(const float4*)(bias + nb);
            float4 b1 = *(const float4*)(bias + nb + 4);
            float4 o0;
            float4 o1;
            o0.x = scr[r*16 + ch*8 + 0] + b0.x + x0.x;
            o0.y = scr[r*16 + ch*8 + 1] + b0.y + x0.y;
            o0.z = scr[r*16 + ch*8 + 2] + b0.z + x0.z;
            o0.w = scr[r*16 + ch*8 + 3] + b0.w + x0.w;
            o1.x = scr[r*16 + ch*8 + 4] + b1.x + x1.x;
            o1.y = scr[r*16 + ch*8 + 5] + b1.y + x1.y;
            o1.z = scr[r*16 + ch*8 + 6] + b1.z + x1.z;
            o1.w = scr[r*16 + ch*8 + 7] + b1.w + x1.w;
            *(float4*)(out + (size_t)m * Cn + nb) = o0;
            *(float4*)(out + (size_t)m * Cn + nb + 4) = o1;
            __syncwarp();
        }
    }
}

// -------------------- launch -------------------------------------------------
extern "C" void kernel_launch(void* const* d_in, const int* in_sizes, int n_in,
                              void* d_out, int out_size) {
    const float* x     = (const float*)d_in[0];
    const float* gamma = (const float*)d_in[1];
    const float* beta  = (const float*)d_in[2];
    const float* w_qkv = (const float*)d_in[3];
    const float* w_out = (const float*)d_in[4];
    const float* b_out = (const float*)d_in[5];
    float* out = (float*)d_out;

    gn_part_kernel<<<dim3(8, Bn), 256>>>(x);
    gn_fin_kernel<<<1, 32>>>();
    qkv_wmma_kernel<<<dim3(128, 3), 256>>>(x, gamma, beta, w_qkv);
    attn_wmma_kernel<<<dim3(Sn / 128, Hn, Bn * NSPLIT), 128>>>();
    out_wmma_kernel<<<128, 256>>>(x, w_out, b_out, out);
}

// round 16
// speedup vs baseline: 1.0639x; 1.0357x over previous
#include <cuda_runtime.h>
#include <cuda_fp16.h>
#include <mma.h>
#include <cstdint>
#include <string.h>

using namespace nvcuda;

#define Bn 8
#define Sn 2048
#define Cn 128
#define Hn 4
#define Dn 32
#define HD (Hn*Dn)
#define NSPLIT 2
#define KEYS_PER_SPLIT (Sn/NSPLIT)

// -------------------- scratch ------------------------------------------------
__device__ float g_mu[Bn];
__device__ float g_rstd[Bn];
__device__ float g_part[Bn*8*2];
__device__ __half g_qh[Bn*Hn*Sn*Dn];   // [B,H,S,D], pre-scaled by D^-0.5*log2(e)
__device__ __half g_kh[Bn*Hn*Sn*Dn];
__device__ __half g_vh[Bn*Hn*Sn*Dn];
__device__ float g_po[NSPLIT*Bn*Hn*Sn*Dn];  // partial O (unnormalized, f32)
__device__ float g_pl[NSPLIT*Bn*Hn*Sn];     // partial rowsum

// -------------------- kernel 1a: GroupNorm partial sums ----------------------
__global__ __launch_bounds__(256) void gn_part_kernel(const float* __restrict__ x) {
    const int sl = blockIdx.x;
    const int b  = blockIdx.y;
    const int n4 = Sn * Cn / 4;
    const int per = n4 / 8;
    const float4* xb = (const float4*)(x + (size_t)b * Sn * Cn) + sl * per;
    float s = 0.f;
    float ss = 0.f;
    for (int i = threadIdx.x; i < per; i += 256) {
        float4 v = xb[i];
        s  += v.x + v.y + v.z + v.w;
        ss += v.x*v.x + v.y*v.y + v.z*v.z + v.w*v.w;
    }
    __shared__ float sh[256];
    __shared__ float sh2[256];
    sh[threadIdx.x] = s;
    sh2[threadIdx.x] = ss;
    __syncthreads();
    for (int st = 128; st > 0; st >>= 1) {
        if (threadIdx.x < st) {
            sh[threadIdx.x]  += sh[threadIdx.x + st];
            sh2[threadIdx.x] += sh2[threadIdx.x + st];
        }
        __syncthreads();
    }
    if (threadIdx.x == 0) {
        g_part[(b*8 + sl)*2 + 0] = sh[0];
        g_part[(b*8 + sl)*2 + 1] = sh2[0];
    }
}

// -------------------- kernel 1b: GroupNorm finalize --------------------------
__global__ void gn_fin_kernel() {
    int b = threadIdx.x;
    if (b < Bn) {
        float s = 0.f;
        float ss = 0.f;
        for (int i = 0; i < 8; i++) {
            s  += g_part[(b*8 + i)*2 + 0];
            ss += g_part[(b*8 + i)*2 + 1];
        }
        const float inv_n = 1.0f / (float)(Sn * Cn);
        float mu  = s * inv_n;
        float var = ss * inv_n - mu * mu;
        g_mu[b]   = mu;
        g_rstd[b] = rsqrtf(var + 1e-5f);
    }
}

// -------------------- kernel 2: norm + QKV GEMM (half wmma) ------------------
__global__ __launch_bounds__(256) void qkv_wmma_kernel(
    const float* __restrict__ x, const float* __restrict__ gamma,
    const float* __restrict__ beta, const float* __restrict__ w)
{
    __shared__ __half As[128*72];
    __shared__ __half Bs[128*72];
    __shared__ float Scr[8*256];

    const int m0 = blockIdx.x * 128;
    const int part = blockIdx.y;
    const int n0 = part * 128;
    const int b  = m0 >> 11;
    const float mu = g_mu[b];
    const float rstd = g_rstd[b];
    const int t = threadIdx.x;
    const int wid = t >> 5;
    const int lane = t & 31;
    const int wm = wid >> 1;
    const int wn = wid & 1;

    wmma::fragment<wmma::accumulator, 16, 16, 16, float> acc[2][4];
    #pragma unroll
    for (int i = 0; i < 2; i++) {
        #pragma unroll
        for (int j = 0; j < 4; j++) {
            wmma::fill_fragment(acc[i][j], 0.f);
        }
    }

    for (int kc = 0; kc < Cn; kc += 64) {
        __syncthreads();
        #pragma unroll
        for (int it = 0; it < 8; it++) {
            int idx = it * 256 + t;
            int r = idx >> 4;
            int c4 = idx & 15;
            float4 xv = *(const float4*)(x + (size_t)(m0 + r) * Cn + kc + c4 * 4);
            float4 gv = *(const float4*)(gamma + kc + c4 * 4);
            float4 bv = *(const float4*)(beta  + kc + c4 * 4);
            __half* ap = As + r*72 + c4*4;
            ap[0] = __float2half((xv.x - mu) * rstd * gv.x + bv.x);
            ap[1] = __float2half((xv.y - mu) * rstd * gv.y + bv.y);
            ap[2] = __float2half((xv.z - mu) * rstd * gv.z + bv.z);
            ap[3] = __float2half((xv.w - mu) * rstd * gv.w + bv.w);
            float4 wv = *(const float4*)(w + (size_t)(n0 + r) * Cn + kc + c4 * 4);
            __half* bp = Bs + r*72 + c4*4;
            bp[0] = __float2half(wv.x);
            bp[1] = __float2half(wv.y);
            bp[2] = __float2half(wv.z);
            bp[3] = __float2half(wv.w);
        }
        __syncthreads();
        #pragma unroll
        for (int ks = 0; ks < 4; ks++) {
            wmma::fragment<wmma::matrix_a, 16, 16, 16, __half, wmma::row_major> af[2];
            #pragma unroll
            for (int i = 0; i < 2; i++) {
                wmma::load_matrix_sync(af[i], As + (wm*32 + i*16)*72 + ks*16, 72);
            }
            #pragma unroll
            for (int j = 0; j < 4; j++) {
                wmma::fragment<wmma::matrix_b, 16, 16, 16, __half, wmma::col_major> bf;
                wmma::load_matrix_sync(bf, Bs + (wn*64 + j*16)*72 + ks*16, 72);
                wmma::mma_sync(acc[0][j], af[0], bf, acc[0][j]);
                wmma::mma_sync(acc[1][j], af[1], bf, acc[1][j]);
            }
        }
    }

    const float qscale = 0.17677669529663689f * 1.4426950408889634f;
    const float scale = (part == 0) ? qscale : 1.0f;
    __half* dstbase = (part == 0) ? g_qh : ((part == 1) ? g_kh : g_vh);
    float* scr = Scr + wid * 256;
    const int r = lane & 15;
    const int ch = lane >> 4;
    #pragma unroll
    for (int i = 0; i < 2; i++) {
        #pragma unroll
        for (int j = 0; j < 4; j++) {
            wmma::store_matrix_sync(scr, acc[i][j], 16, wmma::mem_row_major);
            __syncwarp();
            int m = m0 + wm*32 + i*16 + r;
            int s = m & (Sn - 1);
            int nb = wn*64 + j*16 + ch*8;
            int h = nb >> 5;
            int d = nb & 31;
            __half tmp[8];
            #pragma unroll
            for (int cc = 0; cc < 8; cc++) {
                tmp[cc] = __float2half(scr[r*16 + ch*8 + cc] * scale);
            }
            __half* dst = dstbase + (((size_t)(b*Hn + h)) * Sn + s) * Dn + d;
            *(uint4*)dst = *(uint4*)tmp;
            __syncwarp();
        }
    }
}

// -------------------- kernel 3: flash attention (split-K x2, R13 config) -----
// grid (S/128, H, B*2), block 128 = 4 warps, 32 q-rows per warp
__global__ __launch_bounds__(128) void attn_wmma_kernel() {
    __shared__ __half SB[2*64*40];          // Ks + Vs (pitch 40); Q staged here first
    __shared__ __half Ones[16*24];          // 16x16 block, col 0 = 1.0 (pitch 24)
    __shared__ __half Pb[4*2*16*72];        // per-warp 2 P tiles / epilogue scratch

    const int qt = blockIdx.x;
    const int h  = blockIdx.y;
    const int bz = blockIdx.z;
    const int b  = bz >> 1;
    const int split = bz & 1;
    const int bh = b * Hn + h;
    const size_t base = (size_t)bh * Sn * Dn;
    const int t = threadIdx.x;
    const int wid = t >> 5;
    const int lane = t & 31;

    __half* Ks = SB;
    __half* Vs = SB + 64*40;
    __half* Pw = Pb + wid * 2 * 16 * 72;

    // stage Q (128 x 32 half) over Ks|Vs, pitch 40; init Ones block
    {
        const uint4* qsrc = (const uint4*)(g_qh + base + (size_t)qt * 128 * Dn);
        #pragma unroll
        for (int it = 0; it < 4; it++) {
            int idx = it * 128 + t;
            int r = idx >> 2;
            int c = idx & 3;
            *(uint4*)&SB[r*40 + c*8] = qsrc[idx];
        }
        if (t < 48) {
            int r = t / 3;
            int c8 = t - r * 3;
            __half z[8];
            #pragma unroll
            for (int j = 0; j < 8; j++) {
                z[j] = __float2half(0.f);
            }
            if (c8 == 0) {
                z[0] = __float2half(1.f);
            }
            *(uint4*)&Ones[r*24 + c8*8] = *(uint4*)z;
        }
    }
    __syncthreads();

    wmma::fragment<wmma::matrix_a, 16, 16, 16, __half, wmma::row_major> qfrag[2][2];
    #pragma unroll
    for (int qg = 0; qg < 2; qg++) {
        #pragma unroll
        for (int kc = 0; kc < 2; kc++) {
            wmma::load_matrix_sync(qfrag[qg][kc], SB + (wid*32 + qg*16)*40 + kc*16, 40);
        }
    }
    wmma::fragment<wmma::matrix_b, 16, 16, 16, __half, wmma::row_major> onesfrag;
    wmma::load_matrix_sync(onesfrag, Ones, 24);
    __syncthreads();

    // persistent accumulators
    wmma::fragment<wmma::accumulator, 16, 16, 16, float> oacc[2][2];
    wmma::fragment<wmma::accumulator, 16, 16, 16, float> racc[2];
    #pragma unroll
    for (int qg = 0; qg < 2; qg++) {
        wmma::fill_fragment(oacc[qg][0], 0.f);
        wmma::fill_fragment(oacc[qg][1], 0.f);
        wmma::fill_fragment(racc[qg], 0.f);
    }

    const uint4* ksrc = (const uint4*)(g_kh + base + (size_t)split * KEYS_PER_SPLIT * Dn);
    const uint4* vsrc = (const uint4*)(g_vh + base + (size_t)split * KEYS_PER_SPLIT * Dn);
    const int c_s = t & 3;
    uint4 kreg[2];
    uint4 vreg[2];
    #pragma unroll
    for (int it = 0; it < 2; it++) {
        kreg[it] = ksrc[it*128 + t];
        vreg[it] = vsrc[it*128 + t];
    }

    const int NT = KEYS_PER_SPLIT / 64;   // 16
    for (int kb = 0; kb < NT; kb++) {
        __syncthreads();
        #pragma unroll
        for (int it = 0; it < 2; it++) {
            int r = (it * 128 + t) >> 2;
            *(uint4*)&Ks[r*40 + c_s*8] = kreg[it];
            *(uint4*)&Vs[r*40 + c_s*8] = vreg[it];
        }
        __syncthreads();
        if (kb + 1 < NT) {
            #pragma unroll
            for (int it = 0; it < 2; it++) {
                kreg[it] = ksrc[(kb+1)*256 + it*128 + t];
                vreg[it] = vsrc[(kb+1)*256 + it*128 + t];
            }
        }

        // S = Q K^T for both q-groups (kfrag loaded once per nt, used twice)
        #pragma unroll
        for (int nt = 0; nt < 4; nt++) {
            wmma::fragment<wmma::matrix_b, 16, 16, 16, __half, wmma::col_major> kf0;
            wmma::fragment<wmma::matrix_b, 16, 16, 16, __half, wmma::col_major> kf1;
            wmma::load_matrix_sync(kf0, Ks + (nt*16)*40, 40);
            wmma::load_matrix_sync(kf1, Ks + (nt*16)*40 + 16, 40);
            #pragma unroll
            for (int qg = 0; qg < 2; qg++) {
                wmma::fragment<wmma::accumulator, 16, 16, 16, __half> cacc;
                wmma::fill_fragment(cacc, __float2half(0.f));
                wmma::mma_sync(cacc, qfrag[qg][0], kf0, cacc);
                wmma::mma_sync(cacc, qfrag[qg][1], kf1, cacc);
                #pragma unroll
                for (int i = 0; i < cacc.num_elements / 2; i++) {
                    __half2 hv = __halves2half2(cacc.x[2*i], cacc.x[2*i+1]);
                    hv = h2exp2(hv);
                    cacc.x[2*i]   = __low2half(hv);
                    cacc.x[2*i+1] = __high2half(hv);
                }
                wmma::store_matrix_sync(Pw + qg*(16*72) + nt*16, cacc, 72, wmma::mem_row_major);
            }
        }
        __syncwarp();

        // O += P V ; rowsum += P ones
        #pragma unroll
        for (int kc = 0; kc < 4; kc++) {
            wmma::fragment<wmma::matrix_a, 16, 16, 16, __half, wmma::row_major> pf0;
            wmma::fragment<wmma::matrix_a, 16, 16, 16, __half, wmma::row_major> pf1;
            wmma::load_matrix_sync(pf0, Pw + kc*16, 72);
            wmma::load_matrix_sync(pf1, Pw + 16*72 + kc*16, 72);
            wmma::fragment<wmma::matrix_b, 16, 16, 16, __half, wmma::row_major> vfrag;
            wmma::load_matrix_sync(vfrag, Vs + (kc*16)*40, 40);
            wmma::mma_sync(oacc[0][0], pf0, vfrag, oacc[0][0]);
            wmma::mma_sync(oacc[1][0], pf1, vfrag, oacc[1][0]);
            wmma::load_matrix_sync(vfrag, Vs + (kc*16)*40 + 16, 40);
            wmma::mma_sync(oacc[0][1], pf0, vfrag, oacc[0][1]);
            wmma::mma_sync(oacc[1][1], pf1, vfrag, oacc[1][1]);
            wmma::mma_sync(racc[0], pf0, onesfrag, racc[0]);
            wmma::mma_sync(racc[1], pf1, onesfrag, racc[1]);
        }
        __syncwarp();
    }

    // epilogue: write f32 partial O directly from fragments, rowsum via smem
    float* pobase = g_po + ((size_t)split * (Bn*Hn) + bh) * Sn * Dn;
    float* plbase = g_pl + ((size_t)split * (Bn*Hn) + bh) * Sn;
    float* scr = (float*)Pw;
    #pragma unroll
    for (int qg = 0; qg < 2; qg++) {
        int qrow0 = qt*128 + wid*32 + qg*16;
        wmma::store_matrix_sync(pobase + (size_t)qrow0 * Dn,      oacc[qg][0], Dn, wmma::mem_row_major);
        wmma::store_matrix_sync(pobase + (size_t)qrow0 * Dn + 16, oacc[qg][1], Dn, wmma::mem_row_major);
        wmma::store_matrix_sync(scr, racc[qg], 16, wmma::mem_row_major);
        __syncwarp();
        if (lane < 16) {
            plbase[qrow0 + lane] = scr[lane*16];
        }
        __syncwarp();
    }
}

// -------------------- kernel 4: combine + out projection + residual ----------
// grid (128), block 256; A tile built from 2 split partials (normalize inline)
__global__ __launch_bounds__(256) void out_wmma_kernel(
    const float* __restrict__ x, const float* __restrict__ w,
    const float* __restrict__ bias, float* __restrict__ out)
{
    __shared__ __half As[128*72];
    __shared__ __half Bs[128*72];
    __shared__ float Scr[8*256];

    const int m0 = blockIdx.x * 128;
    const int t = threadIdx.x;
    const int wid = t >> 5;
    const int lane = t & 31;
    const int wm = wid >> 1;
    const int wn = wid & 1;

    const size_t stride_o = (size_t)(Bn*Hn) * Sn * Dn;
    const size_t stride_l = (size_t)(Bn*Hn) * Sn;

    wmma::fragment<wmma::accumulator, 16, 16, 16, float> acc[2][4];
    #pragma unroll
    for (int i = 0; i < 2; i++) {
        #pragma unroll
        for (int j = 0; j < 4; j++) {
            wmma::fill_fragment(acc[i][j], 0.f);
        }
    }

    for (int kc = 0; kc < HD; kc += 64) {
        __syncthreads();
        // A: combine 2 split partials, normalize, convert to half
        #pragma unroll
        for (int it = 0; it < 4; it++) {
            int idx = it * 256 + t;       // 0..1023, 8 cols each
            int r = idx >> 3;
            int c8 = idx & 7;
            int m = m0 + r;
            int b = m >> 11;
            int s = m & (Sn - 1);
            int col = kc + c8*8;
            int h = col >> 5;
            int d = col & 31;
            size_t po_off = ((size_t)(b*Hn + h) * Sn + s) * Dn + d;
            size_t pl_off = (size_t)(b*Hn + h) * Sn + s;
            const float4* p0 = (const float4*)(g_po + po_off);
            const float4* p1 = (const float4*)(g_po + stride_o + po_off);
            float il = 1.0f / (g_pl[pl_off] + g_pl[stride_l + pl_off]);
            float4 a0 = p0[0];
            float4 a1 = p0[1];
            float4 b0 = p1[0];
            float4 b1 = p1[1];
            __half tmp[8];
            tmp[0] = __float2half((a0.x + b0.x) * il);
            tmp[1] = __float2half((a0.y + b0.y) * il);
            tmp[2] = __float2half((a0.z + b0.z) * il);
            tmp[3] = __float2half((a0.w + b0.w) * il);
            tmp[4] = __float2half((a1.x + b1.x) * il);
            tmp[5] = __float2half((a1.y + b1.y) * il);
            tmp[6] = __float2half((a1.z + b1.z) * il);
            tmp[7] = __float2half((a1.w + b1.w) * il);
            *(uint4*)&As[r*72 + c8*8] = *(uint4*)tmp;
        }
        // B: w f32 -> half
        #pragma unroll
        for (int it = 0; it < 8; it++) {
            int idx = it * 256 + t;
            int r = idx >> 4;
            int c4 = idx & 15;
            float4 wv = *(const float4*)(w + (size_t)r * HD + kc + c4 * 4);
            __half* bp = Bs + r*72 + c4*4;
            bp[0] = __float2half(wv.x);
            bp[1] = __float2half(wv.y);
            bp[2] = __float2half(wv.z);
            bp[3] = __float2half(wv.w);
        }
        __syncthreads();
        #pragma unroll
        for (int ks = 0; ks < 4; ks++) {
            wmma::fragment<wmma::matrix_a, 16, 16, 16, __half, wmma::row_major> af[2];
            #pragma unroll
            for (int i = 0; i < 2; i++) {
                wmma::load_matrix_sync(af[i], As + (wm*32 + i*16)*72 + ks*16, 72);
            }
            #pragma unroll
            for (int j = 0; j < 4; j++) {
                wmma::fragment<wmma::matrix_b, 16, 16, 16, __half, wmma::col_major> bf;
                wmma::load_matrix_sync(bf, Bs + (wn*64 + j*16)*72 + ks*16, 72);
                wmma::mma_sync(acc[0][j], af[0], bf, acc[0][j]);
                wmma::mma_sync(acc[1][j], af[1], bf, acc[1][j]);
            }
        }
    }

    float* scr = Scr + wid * 256;
    const int r = lane & 15;
    const int ch = lane >> 4;
    #pragma unroll
    for (int i = 0; i < 2; i++) {
        #pragma unroll
        for (int j = 0; j < 4; j++) {
            wmma::store_matrix_sync(scr, acc[i][j], 16, wmma::mem_row_major);
            __syncwarp();
            int m = m0 + wm*32 + i*16 + r;
            int nb = wn*64 + j*16 + ch*8;
            float4 x0 = *(const float4*)(x + (size_t)m * Cn + nb);
            float4 x1 = *(const float4*)(x + (size_t)m * Cn + nb + 4);
            float4 b0 = *(const float4*)(bias + nb);
            float4 b1 = *(const float4*)(bias + nb + 4);
            float4 o0;
            float4 o1;
            o0.x = scr[r*16 + ch*8 + 0] + b0.x + x0.x;
            o0.y = scr[r*16 + ch*8 + 1] + b0.y + x0.y;
            o0.z = scr[r*16 + ch*8 + 2] + b0.z + x0.z;
            o0.w = scr[r*16 + ch*8 + 3] + b0.w + x0.w;
            o1.x = scr[r*16 + ch*8 + 4] + b1.x + x1.x;
            o1.y = scr[r*16 + ch*8 + 5] + b1.y + x1.y;
            o1.z = scr[r*16 + ch*8 + 6] + b1.z + x1.z;
            o1.w = scr[r*16 + ch*8 + 7] + b1.w + x1.w;
            *(float4*)(out + (size_t)m * Cn + nb) = o0;
            *(float4*)(out + (size_t)m * Cn + nb + 4) = o1;
            __syncwarp();
        }
    }
}

// -------------------- launch -------------------------------------------------
extern "C" void kernel_launch(void* const* d_in, const int* in_sizes, int n_in,
                              void* d_out, int out_size) {
    const float* x     = (const float*)d_in[0];
    const float* gamma = (const float*)d_in[1];
    const float* beta  = (const float*)d_in[2];
    const float* w_qkv = (const float*)d_in[3];
    const float* w_out = (const float*)d_in[4];
    const float* b_out = (const float*)d_in[5];
    float* out = (float*)d_out;

    gn_part_kernel<<<dim3(8, Bn), 256>>>(x);
    gn_fin_kernel<<<1, 32>>>();
    qkv_wmma_kernel<<<dim3(128, 3), 256>>>(x, gamma, beta, w_qkv);
    attn_wmma_kernel<<<dim3(Sn / 128, Hn, Bn * NSPLIT), 128>>>();
    out_wmma_kernel<<<128, 256>>>(x, w_out, b_out, out);
}